// round 3
// baseline (speedup 1.0000x reference)
#include <cuda_runtime.h>
#include <math_constants.h>

#define DIM   64
#define KCODE 1024
#define MAXN  262144
#define EPS_AMB 8e-5f

typedef unsigned long long u64;

// Scratch (no cudaMalloc allowed)
__device__ int    g_idx[MAXN];
__device__ float  g_wsum2[KCODE];
__device__ double g_loss;
__device__ int    g_flagn;
__device__ int    g_flags[MAXN];

// ---------------------------------------------------------------------------
__device__ __forceinline__ u64 pack2(float lo, float hi) {
    u64 r;
    asm("mov.b64 %0, {%1,%2};" : "=l"(r) : "f"(lo), "f"(hi));
    return r;
}
__device__ __forceinline__ void unpack2(u64 v, float& lo, float& hi) {
    asm("mov.b64 {%0,%1}, %2;" : "=f"(lo), "=f"(hi) : "l"(v));
}
#define FMA2(acc, a, b) \
    asm("fma.rn.f32x2 %0, %1, %2, %3;" : "=l"(acc) : "l"(a), "l"(b), "l"(acc))

// ---------------------------------------------------------------------------
__global__ void k_zero()
{
    g_loss  = 0.0;
    g_flagn = 0;
}

// ---------------------------------------------------------------------------
// b_k = sum_d fl(w*w), sequential ascending d (mirrors jnp.sum(weight**2,1))
__global__ void k_wsum2(const float* __restrict__ w)
{
    int k = blockIdx.x * blockDim.x + threadIdx.x;
    if (k < KCODE) {
        const float* r = w + (size_t)k * DIM;
        float s = 0.0f;
        #pragma unroll
        for (int d = 0; d < DIM; ++d)
            s = __fadd_rn(s, __fmul_rn(r[d], r[d]));
        g_wsum2[k] = s;
    }
}

// ---------------------------------------------------------------------------
// Approximate argmin via packed f32x2 FMA (2 scalar chains per code).
// Score u_k = b_k - 2*dot~_k  (token-constant ||z||^2 omitted: it cannot
// change the argmin ordering except through the reference's own rounding,
// which is covered by the EPS_AMB ambiguity window + exact fallback).
__global__ __launch_bounds__(256, 2)
void k_argmin(const float* __restrict__ z,
              const float* __restrict__ w,
              float* __restrict__ out_idx)
{
    __shared__ float4 sW4[32 * (DIM / 4)];   // 8 KB code tile (32 codes)
    __shared__ float  sB[32];

    const int tid = threadIdx.x;
    const size_t token = (size_t)blockIdx.x * 256 + tid;

    // z row -> packed f32x2 registers
    u64 zp[DIM / 2];
    {
        const float4* zsrc = (const float4*)(z + token * DIM);
        #pragma unroll
        for (int i = 0; i < DIM / 4; ++i) {
            float4 v = zsrc[i];
            zp[2 * i + 0] = pack2(v.x, v.y);
            zp[2 * i + 1] = pack2(v.z, v.w);
        }
    }

    float m1 = CUDART_INF_F;   // smallest u
    float m2 = CUDART_INF_F;   // second smallest u
    int   k1 = 0;

    for (int kt = 0; kt < KCODE / 32; ++kt) {
        __syncthreads();
        {
            const float4* wsrc = (const float4*)(w + (size_t)kt * 32 * DIM);
            sW4[tid]       = wsrc[tid];
            sW4[tid + 256] = wsrc[tid + 256];
            if (tid < 32) sB[tid] = g_wsum2[kt * 32 + tid];
        }
        __syncthreads();

        #pragma unroll 1
        for (int k = 0; k < 32; k += 4) {
            const ulonglong2* w0 = (const ulonglong2*)(sW4 + (k + 0) * (DIM / 4));
            const ulonglong2* w1 = (const ulonglong2*)(sW4 + (k + 1) * (DIM / 4));
            const ulonglong2* w2 = (const ulonglong2*)(sW4 + (k + 2) * (DIM / 4));
            const ulonglong2* w3 = (const ulonglong2*)(sW4 + (k + 3) * (DIM / 4));
            u64 acc0 = 0, acc1 = 0, acc2 = 0, acc3 = 0;  // 0x0 == packed {0.f,0.f}
            #pragma unroll
            for (int q = 0; q < DIM / 4; ++q) {
                const ulonglong2 v0 = w0[q], v1 = w1[q], v2 = w2[q], v3 = w3[q];
                const u64 za = zp[2 * q + 0], zb = zp[2 * q + 1];
                FMA2(acc0, za, v0.x);
                FMA2(acc1, za, v1.x);
                FMA2(acc2, za, v2.x);
                FMA2(acc3, za, v3.x);
                FMA2(acc0, zb, v0.y);
                FMA2(acc1, zb, v1.y);
                FMA2(acc2, zb, v2.y);
                FMA2(acc3, zb, v3.y);
            }
            const int kb = kt * 32 + k;
            float lo, hi, u;
            unpack2(acc0, lo, hi); u = __fmaf_rn(-2.0f, lo + hi, sB[k + 0]);
            if (u < m1) { m2 = m1; m1 = u; k1 = kb + 0; } else if (u < m2) m2 = u;
            unpack2(acc1, lo, hi); u = __fmaf_rn(-2.0f, lo + hi, sB[k + 1]);
            if (u < m1) { m2 = m1; m1 = u; k1 = kb + 1; } else if (u < m2) m2 = u;
            unpack2(acc2, lo, hi); u = __fmaf_rn(-2.0f, lo + hi, sB[k + 2]);
            if (u < m1) { m2 = m1; m1 = u; k1 = kb + 2; } else if (u < m2) m2 = u;
            unpack2(acc3, lo, hi); u = __fmaf_rn(-2.0f, lo + hi, sB[k + 3]);
            if (u < m1) { m2 = m1; m1 = u; k1 = kb + 3; } else if (u < m2) m2 = u;
        }
    }

    g_idx[token]   = k1;
    out_idx[token] = (float)k1;

    // Ambiguous: runner-up within the provable error window -> exact fallback
    if (m2 - m1 <= EPS_AMB) {
        int p = atomicAdd(&g_flagn, 1);
        g_flags[p] = (int)token;
    }
}

// ---------------------------------------------------------------------------
// Exact fallback: bit-exact reference semantics for flagged tokens.
// One warp per token; lane handles codes k = lane + 32j, 4 parallel exact
// sequential chains; warp-reduce (val, idx) with first-index tie-break.
__global__ __launch_bounds__(256)
void k_exact(const float* __restrict__ z,
             const float* __restrict__ w,
             float* __restrict__ out_idx)
{
    const int lane = threadIdx.x & 31;
    const int gw   = (blockIdx.x * blockDim.x + threadIdx.x) >> 5;
    const int nw   = (gridDim.x * blockDim.x) >> 5;
    const int nflag = g_flagn;

    for (int i = gw; i < nflag; i += nw) {
        const size_t token = (size_t)g_flags[i];

        // z row (warp-uniform loads), plus exact a = sum fl(z*z)
        float zr[DIM];
        float a = 0.0f;
        #pragma unroll
        for (int d = 0; d < DIM; ++d) {
            zr[d] = z[token * DIM + d];
            a = __fadd_rn(a, __fmul_rn(zr[d], zr[d]));
        }

        float best = CUDART_INF_F;
        int   bidx = 0;

        for (int k0 = lane; k0 < KCODE; k0 += 128) {
            const float* w0 = w + (size_t)(k0 +  0) * DIM;
            const float* w1 = w + (size_t)(k0 + 32) * DIM;
            const float* w2 = w + (size_t)(k0 + 64) * DIM;
            const float* w3 = w + (size_t)(k0 + 96) * DIM;
            float d0 = 0.0f, d1 = 0.0f, d2 = 0.0f, d3 = 0.0f;
            #pragma unroll
            for (int d = 0; d < DIM; ++d) {
                const float zv = zr[d];
                d0 = __fmaf_rn(zv, w0[d], d0);
                d1 = __fmaf_rn(zv, w1[d], d1);
                d2 = __fmaf_rn(zv, w2[d], d2);
                d3 = __fmaf_rn(zv, w3[d], d3);
            }
            float t, dd;
            t  = __fadd_rn(a, g_wsum2[k0]);
            dd = __fadd_rn(t, -__fmul_rn(2.0f, d0));
            if (dd < best) { best = dd; bidx = k0; }
            t  = __fadd_rn(a, g_wsum2[k0 + 32]);
            dd = __fadd_rn(t, -__fmul_rn(2.0f, d1));
            if (dd < best) { best = dd; bidx = k0 + 32; }
            t  = __fadd_rn(a, g_wsum2[k0 + 64]);
            dd = __fadd_rn(t, -__fmul_rn(2.0f, d2));
            if (dd < best) { best = dd; bidx = k0 + 64; }
            t  = __fadd_rn(a, g_wsum2[k0 + 96]);
            dd = __fadd_rn(t, -__fmul_rn(2.0f, d3));
            if (dd < best) { best = dd; bidx = k0 + 96; }
        }

        // warp reduce: min value, ties -> smallest index (= first occurrence)
        #pragma unroll
        for (int off = 16; off > 0; off >>= 1) {
            float ov = __shfl_down_sync(0xffffffffu, best, off);
            int   oi = __shfl_down_sync(0xffffffffu, bidx, off);
            if (ov < best || (ov == best && oi < bidx)) { best = ov; bidx = oi; }
        }
        if (lane == 0) {
            g_idx[token]   = bidx;
            out_idx[token] = (float)bidx;
        }
    }
}

// ---------------------------------------------------------------------------
// Gather z_q_st = fl(z + fl(w[idx] - z)), loss sum in double.
// 512 threads = 32 tokens/block, 16 lanes per token (coalesced float4).
// Warp shuffle reduction, one atomic per block.
__global__ __launch_bounds__(512)
void k_gather(const float* __restrict__ z,
              const float* __restrict__ w,
              float* __restrict__ out_zq)
{
    __shared__ double sred[16];
    const int tid = threadIdx.x;
    const size_t token = (size_t)blockIdx.x * 32 + (tid >> 4);
    const int c = tid & 15;

    const int idx = g_idx[token];
    const float4 wv = ((const float4*)(w + (size_t)idx * DIM))[c];
    const float4 zv = ((const float4*)(z + token * DIM))[c];

    const float dx = __fsub_rn(wv.x, zv.x);
    const float dy = __fsub_rn(wv.y, zv.y);
    const float dz = __fsub_rn(wv.z, zv.z);
    const float dw = __fsub_rn(wv.w, zv.w);

    float4 o;
    o.x = __fadd_rn(zv.x, dx);
    o.y = __fadd_rn(zv.y, dy);
    o.z = __fadd_rn(zv.z, dz);
    o.w = __fadd_rn(zv.w, dw);
    ((float4*)out_zq)[token * (DIM / 4) + c] = o;

    double s = (double)__fmul_rn(dx, dx);
    s += (double)__fmul_rn(dy, dy);
    s += (double)__fmul_rn(dz, dz);
    s += (double)__fmul_rn(dw, dw);

    #pragma unroll
    for (int off = 16; off > 0; off >>= 1)
        s += __shfl_down_sync(0xffffffffu, s, off);

    const int wid = tid >> 5;
    if ((tid & 31) == 0) sred[wid] = s;
    __syncthreads();

    if (wid == 0) {
        double v = (tid < 16) ? sred[tid] : 0.0;
        #pragma unroll
        for (int off = 8; off > 0; off >>= 1)
            v += __shfl_down_sync(0xffffffffu, v, off);
        if (tid == 0) atomicAdd(&g_loss, v);
    }
}

// ---------------------------------------------------------------------------
__global__ void k_final(float* __restrict__ out_loss, int total_elems)
{
    const float m = (float)(g_loss / (double)total_elems);
    out_loss[0] = __fadd_rn(m, __fmul_rn(0.25f, m));
}

// ---------------------------------------------------------------------------
extern "C" void kernel_launch(void* const* d_in, const int* in_sizes, int n_in,
                              void* d_out, int out_size)
{
    const float* z = (const float*)d_in[0];   // (N, 64) fp32
    const float* w = (const float*)d_in[1];   // (1024, 64) fp32

    const int ND = in_sizes[0];
    const int N  = ND / DIM;                  // 262144

    float* out      = (float*)d_out;
    float* out_zq   = out;                    // N*64 floats
    float* out_loss = out + (size_t)N * DIM;  // 1 float
    float* out_idx  = out_loss + 1;           // N floats

    k_zero<<<1, 1>>>();
    k_wsum2<<<(KCODE + 255) / 256, 256>>>(w);
    k_argmin<<<N / 256, 256>>>(z, w, out_idx);
    k_exact<<<256, 256>>>(z, w, out_idx);
    k_gather<<<N / 32, 512>>>(z, w, out_zq);
    k_final<<<1, 1>>>(out_loss, ND);
}

// round 7
// speedup vs baseline: 1.3737x; 1.3737x over previous
#include <cuda_runtime.h>
#include <cuda_bf16.h>
#include <math_constants.h>
#include <cstdint>

#define DIM     64
#define KCODE   1024
#define MAXN    262144
#define EPS_INT 140          // 140 * 2^-21 ~ 6.7e-5 ambiguity window

// ---------------------------------------------------------------------------
// Device scratch (no cudaMalloc allowed)
__device__ int       g_idx[MAXN];
__device__ float     g_wsum2[KCODE];    // exact sequential-chain ||w||^2
__device__ float     g_wsC21[KCODE];    // fl(fl(||w||^2 + 0.25) * 2^21)
__device__ double    g_loss;
__device__ int       g_flagn;
__device__ int       g_flags[MAXN];
// per token: 64 u32 = [z_hi 64bf16 | z_lo 64bf16]  (256 B)
__device__ uint32_t  g_za[(size_t)MAXN * 64];
// per code: 192 bf16 = [w_hi | w_hi | w_lo]        (384 B)
__device__ __nv_bfloat16 g_wb[KCODE * 192];

// ---------------------------------------------------------------------------
__device__ __forceinline__ uint32_t smem_u32(const void* p) {
    uint32_t a;
    asm("{ .reg .u64 t; cvta.to.shared.u64 t, %1; cvt.u32.u64 %0, t; }"
        : "=r"(a) : "l"(p));
    return a;
}
__device__ __forceinline__ void ldsm_x4(uint32_t& r0, uint32_t& r1,
                                        uint32_t& r2, uint32_t& r3, uint32_t addr) {
    asm volatile("ldmatrix.sync.aligned.m8n8.x4.shared.b16 {%0,%1,%2,%3}, [%4];"
                 : "=r"(r0), "=r"(r1), "=r"(r2), "=r"(r3) : "r"(addr));
}
__device__ __forceinline__ void mma_bf16(float* c, const uint32_t* a,
                                         uint32_t b0, uint32_t b1) {
    asm volatile(
        "mma.sync.aligned.m16n8k16.row.col.f32.bf16.bf16.f32 "
        "{%0,%1,%2,%3}, {%4,%5,%6,%7}, {%8,%9}, {%0,%1,%2,%3};"
        : "+f"(c[0]), "+f"(c[1]), "+f"(c[2]), "+f"(c[3])
        : "r"(a[0]), "r"(a[1]), "r"(a[2]), "r"(a[3]), "r"(b0), "r"(b1));
}
__device__ __forceinline__ void cp16(uint32_t dst, const void* src) {
    asm volatile("cp.async.cg.shared.global [%0], [%1], 16;" :: "r"(dst), "l"(src));
}
#define CP_COMMIT() asm volatile("cp.async.commit_group;" ::: "memory")
#define CP_WAIT1()  asm volatile("cp.async.wait_group 1;" ::: "memory")
#define CP_WAIT0()  asm volatile("cp.async.wait_group 0;" ::: "memory")

__device__ __forceinline__ void top2(int& m1, int& m2, int s) {
    int lo = min(m1, s);
    int hi = max(m1, s);
    m1 = lo;
    m2 = min(m2, hi);
}

// ---------------------------------------------------------------------------
__global__ void k_zero() { g_loss = 0.0; g_flagn = 0; }

// ---------------------------------------------------------------------------
__global__ void k_prep_w(const float* __restrict__ w)
{
    int k = blockIdx.x * blockDim.x + threadIdx.x;
    if (k >= KCODE) return;
    const float* r = w + (size_t)k * DIM;
    __nv_bfloat16* dst = g_wb + (size_t)k * 192;
    float s = 0.0f;
    #pragma unroll
    for (int d = 0; d < DIM; ++d) {
        float v = r[d];
        s = __fadd_rn(s, __fmul_rn(v, v));
        __nv_bfloat16 hi = __float2bfloat16(v);
        __nv_bfloat16 lo = __float2bfloat16(__fsub_rn(v, __bfloat162float(hi)));
        dst[d]       = hi;
        dst[64 + d]  = hi;
        dst[128 + d] = lo;
    }
    g_wsum2[k] = s;
    g_wsC21[k] = __fmul_rn(__fadd_rn(s, 0.25f), 2097152.0f);
}

// ---------------------------------------------------------------------------
// z -> [z_hi | z_lo] bf16 rows (256 B/token)
__global__ void k_prep_z(const float* __restrict__ z)
{
    size_t i = (size_t)blockIdx.x * blockDim.x + threadIdx.x;   // float4 index
    float4 v = ((const float4*)z)[i];
    size_t token = i >> 4;
    int q = (int)(i & 15);
    uint32_t* base = g_za + token * 64;

    __nv_bfloat162 h0, h1, l0, l1;
    h0.x = __float2bfloat16(v.x); h0.y = __float2bfloat16(v.y);
    h1.x = __float2bfloat16(v.z); h1.y = __float2bfloat16(v.w);
    l0.x = __float2bfloat16(__fsub_rn(v.x, __bfloat162float(h0.x)));
    l0.y = __float2bfloat16(__fsub_rn(v.y, __bfloat162float(h0.y)));
    l1.x = __float2bfloat16(__fsub_rn(v.z, __bfloat162float(h1.x)));
    l1.y = __float2bfloat16(__fsub_rn(v.w, __bfloat162float(h1.y)));

    uint2 ph; ph.x = *(uint32_t*)&h0; ph.y = *(uint32_t*)&h1;
    uint2 pl; pl.x = *(uint32_t*)&l0; pl.y = *(uint32_t*)&l1;
    ((uint2*)base)[q]        = ph;
    ((uint2*)(base + 32))[q] = pl;
}

// ---------------------------------------------------------------------------
// HMMA argmin filter. 256 tokens/CTA, 8 warps x M32. K=192 (split bf16).
// 8 B-tiles of 128 codes, double-buffered cp.async.
#define SM_A   0            // 256 x 256B = 64 KB
#define SM_B0  65536        // 128 x 384B = 48 KB
#define SM_B1  114688       // 48 KB
#define SM_BC  163840       // 4 KB
#define SMEMSZ 167936

__global__ __launch_bounds__(256, 1)
void k_argmin_mma(float* __restrict__ out_idx)
{
    extern __shared__ char smem[];
    const uint32_t sb = smem_u32(smem);
    const int tid  = threadIdx.x;
    const int lane = tid & 31;
    const int warp = tid >> 5;
    const int t0   = blockIdx.x * 256;

    // Prefetch B tile 0
    {
        const char* src = (const char*)g_wb;
        #pragma unroll
        for (int j = 0; j < 12; ++j) {
            int ic = tid + j * 256;                 // 3072 16B chunks
            int row = ic / 24, c = ic - row * 24;
            cp16(sb + SM_B0 + row * 384 + (((uint32_t)(c ^ (row & 7))) << 4),
                 src + (size_t)ic * 16);
        }
        CP_COMMIT();
    }

    // bC21 table
    for (int i = tid; i < KCODE; i += 256)
        *(float*)(smem + SM_BC + (size_t)i * 4) = g_wsC21[i];

    // Stage A (256 tokens x 256B), XOR-swizzled 16B chunks
    {
        const float4* src = (const float4*)(g_za + (size_t)t0 * 64);
        #pragma unroll
        for (int it = 0; it < 16; ++it) {
            int ic = tid + it * 256;
            int row = ic >> 4, c = ic & 15;
            *(float4*)(smem + SM_A + row * 256 + ((c ^ (row & 7)) << 4)) = src[ic];
        }
    }
    __syncthreads();

    // A fragments (K=128 stored; ksteps 0-3 = z_hi, 4-7 = z_lo)
    uint32_t a[8][2][4];
    {
        const int r16   = lane & 15;
        const int chalf = lane >> 4;
        #pragma unroll
        for (int ks = 0; ks < 8; ++ks)
            #pragma unroll
            for (int mf = 0; mf < 2; ++mf) {
                int row = warp * 32 + mf * 16 + r16;
                int c   = ks * 2 + chalf;
                ldsm_x4(a[ks][mf][0], a[ks][mf][1], a[ks][mf][2], a[ks][mf][3],
                        sb + SM_A + row * 256 + ((c ^ (row & 7)) << 4));
            }
    }

    int m1s[4], m2s[4];
    #pragma unroll
    for (int s = 0; s < 4; ++s) { m1s[s] = 0x7FFFFFFF; m2s[s] = 0x7FFFFFFF; }

    const int brow  = (lane & 7) + ((lane >> 4) << 3);
    const int bc1   = (lane >> 3) & 1;
    const int br7   = brow & 7;
    const int klane = 2 * (lane & 3);

    #pragma unroll 1
    for (int t = 0; t < 8; ++t) {
        __syncthreads();
        if (t + 1 < 8) {
            const char* src = (const char*)g_wb + (size_t)(t + 1) * 128 * 384;
            uint32_t dstb = sb + (((t + 1) & 1) ? SM_B1 : SM_B0);
            #pragma unroll
            for (int j = 0; j < 12; ++j) {
                int ic = tid + j * 256;
                int row = ic / 24, c = ic - row * 24;
                cp16(dstb + row * 384 + (((uint32_t)(c ^ (row & 7))) << 4),
                     src + (size_t)ic * 16);
            }
            CP_COMMIT();
            CP_WAIT1();
        } else {
            CP_WAIT0();
        }
        __syncthreads();

        const uint32_t bab = sb + ((t & 1) ? SM_B1 : SM_B0) + brow * 384;

        #pragma unroll 1
        for (int ng = 0; ng < 8; ++ng) {
            float acc[2][2][4];
            #pragma unroll
            for (int mf = 0; mf < 2; ++mf)
                #pragma unroll
                for (int nf = 0; nf < 2; ++nf)
                    #pragma unroll
                    for (int j = 0; j < 4; ++j) acc[mf][nf][j] = 0.0f;

            const uint32_t bgb = bab + ng * 16 * 384;
            // B fragments: NON-trans ldmatrix (B stored [n][k], TN layout).
            #pragma unroll
            for (int ks = 0; ks < 12; ++ks) {
                uint32_t b0, b1, b2, b3;
                ldsm_x4(b0, b1, b2, b3, bgb + (((ks * 2 + bc1) ^ br7) << 4));
                const int ka = ks & 7;       // 8-11 reuse z_hi frags 0-3
                mma_bf16(acc[0][0], a[ka][0], b0, b1);
                mma_bf16(acc[1][0], a[ka][1], b0, b1);
                mma_bf16(acc[0][1], a[ka][0], b2, b3);
                mma_bf16(acc[1][1], a[ka][1], b2, b3);
            }

            // epilogue: s = rn((b+0.25)*2^21 - 2^22*dot), pack (s<<10)|idx
            const int kb = t * 128 + ng * 16 + klane;
            const float2 bcA = *(const float2*)(smem + SM_BC + (size_t)kb * 4);
            const float2 bcB = *(const float2*)(smem + SM_BC + (size_t)(kb + 8) * 4);
            #pragma unroll
            for (int nf = 0; nf < 2; ++nf) {
                const float2 bc = nf ? bcB : bcA;
                const int kc = kb + nf * 8;
                #pragma unroll
                for (int mf = 0; mf < 2; ++mf) {
                    int s0 = (__float2int_rn(__fmaf_rn(-4194304.0f, acc[mf][nf][0], bc.x)) << 10) | kc;
                    int s1 = (__float2int_rn(__fmaf_rn(-4194304.0f, acc[mf][nf][1], bc.y)) << 10) | (kc + 1);
                    int s2 = (__float2int_rn(__fmaf_rn(-4194304.0f, acc[mf][nf][2], bc.x)) << 10) | kc;
                    int s3 = (__float2int_rn(__fmaf_rn(-4194304.0f, acc[mf][nf][3], bc.y)) << 10) | (kc + 1);
                    top2(m1s[mf * 2],     m2s[mf * 2],     s0);
                    top2(m1s[mf * 2],     m2s[mf * 2],     s1);
                    top2(m1s[mf * 2 + 1], m2s[mf * 2 + 1], s2);
                    top2(m1s[mf * 2 + 1], m2s[mf * 2 + 1], s3);
                }
            }
        }
    }

    // merge across the 4 lanes sharing each row
    #pragma unroll
    for (int s = 0; s < 4; ++s) {
        #pragma unroll
        for (int d = 1; d <= 2; d <<= 1) {
            int om1 = __shfl_xor_sync(0xffffffffu, m1s[s], d);
            int om2 = __shfl_xor_sync(0xffffffffu, m2s[s], d);
            int hi = max(m1s[s], om1);
            m1s[s] = min(m1s[s], om1);
            m2s[s] = min(min(m2s[s], om2), hi);
        }
    }
    if ((lane & 3) == 0) {
        const int q = lane >> 2;
        #pragma unroll
        for (int s = 0; s < 4; ++s) {
            const int token = t0 + warp * 32 + (s >> 1) * 16 + (s & 1) * 8 + q;
            const int k1 = m1s[s] & 1023;
            g_idx[token]   = k1;
            out_idx[token] = (float)k1;
            if ((m2s[s] >> 10) - (m1s[s] >> 10) <= EPS_INT) {
                int p = atomicAdd(&g_flagn, 1);
                g_flags[p] = token;
            }
        }
    }
}

// ---------------------------------------------------------------------------
// Exact fallback: bit-exact reference semantics for flagged tokens.
__global__ __launch_bounds__(256)
void k_exact(const float* __restrict__ z,
             const float* __restrict__ w,
             float* __restrict__ out_idx)
{
    const int lane = threadIdx.x & 31;
    const int gw   = (blockIdx.x * blockDim.x + threadIdx.x) >> 5;
    const int nw   = (gridDim.x * blockDim.x) >> 5;
    const int nflag = g_flagn;

    for (int i = gw; i < nflag; i += nw) {
        const size_t token = (size_t)g_flags[i];

        float zr[DIM];
        float a = 0.0f;
        #pragma unroll
        for (int d = 0; d < DIM; ++d) {
            zr[d] = z[token * DIM + d];
            a = __fadd_rn(a, __fmul_rn(zr[d], zr[d]));
        }

        float best = CUDART_INF_F;
        int   bidx = 0;

        for (int k0 = lane; k0 < KCODE; k0 += 128) {
            const float* w0 = w + (size_t)(k0 +  0) * DIM;
            const float* w1 = w + (size_t)(k0 + 32) * DIM;
            const float* w2 = w + (size_t)(k0 + 64) * DIM;
            const float* w3 = w + (size_t)(k0 + 96) * DIM;
            float d0 = 0.0f, d1 = 0.0f, d2 = 0.0f, d3 = 0.0f;
            #pragma unroll
            for (int d = 0; d < DIM; ++d) {
                const float zv = zr[d];
                d0 = __fmaf_rn(zv, w0[d], d0);
                d1 = __fmaf_rn(zv, w1[d], d1);
                d2 = __fmaf_rn(zv, w2[d], d2);
                d3 = __fmaf_rn(zv, w3[d], d3);
            }
            float tt, dd;
            tt = __fadd_rn(a, g_wsum2[k0]);
            dd = __fadd_rn(tt, -__fmul_rn(2.0f, d0));
            if (dd < best) { best = dd; bidx = k0; }
            tt = __fadd_rn(a, g_wsum2[k0 + 32]);
            dd = __fadd_rn(tt, -__fmul_rn(2.0f, d1));
            if (dd < best) { best = dd; bidx = k0 + 32; }
            tt = __fadd_rn(a, g_wsum2[k0 + 64]);
            dd = __fadd_rn(tt, -__fmul_rn(2.0f, d2));
            if (dd < best) { best = dd; bidx = k0 + 64; }
            tt = __fadd_rn(a, g_wsum2[k0 + 96]);
            dd = __fadd_rn(tt, -__fmul_rn(2.0f, d3));
            if (dd < best) { best = dd; bidx = k0 + 96; }
        }

        #pragma unroll
        for (int off = 16; off > 0; off >>= 1) {
            float ov = __shfl_down_sync(0xffffffffu, best, off);
            int   oi = __shfl_down_sync(0xffffffffu, bidx, off);
            if (ov < best || (ov == best && oi < bidx)) { best = ov; bidx = oi; }
        }
        if (lane == 0) {
            g_idx[token]   = bidx;
            out_idx[token] = (float)bidx;
        }
    }
}

// ---------------------------------------------------------------------------
// Gather z_q_st = fl(z + fl(w[idx] - z)); loss sum in double.
__global__ __launch_bounds__(512)
void k_gather(const float* __restrict__ z,
              const float* __restrict__ w,
              float* __restrict__ out_zq)
{
    __shared__ double sred[16];
    const int tid = threadIdx.x;
    const size_t token = (size_t)blockIdx.x * 32 + (tid >> 4);
    const int c = tid & 15;

    const int idx = g_idx[token];
    const float4 wv = ((const float4*)(w + (size_t)idx * DIM))[c];
    const float4 zv = ((const float4*)(z + token * DIM))[c];

    const float dx = __fsub_rn(wv.x, zv.x);
    const float dy = __fsub_rn(wv.y, zv.y);
    const float dz = __fsub_rn(wv.z, zv.z);
    const float dw = __fsub_rn(wv.w, zv.w);

    float4 o;
    o.x = __fadd_rn(zv.x, dx);
    o.y = __fadd_rn(zv.y, dy);
    o.z = __fadd_rn(zv.z, dz);
    o.w = __fadd_rn(zv.w, dw);
    ((float4*)out_zq)[token * (DIM / 4) + c] = o;

    double s = (double)__fmul_rn(dx, dx);
    s += (double)__fmul_rn(dy, dy);
    s += (double)__fmul_rn(dz, dz);
    s += (double)__fmul_rn(dw, dw);

    #pragma unroll
    for (int off = 16; off > 0; off >>= 1)
        s += __shfl_down_sync(0xffffffffu, s, off);

    const int wrp = tid >> 5;
    if ((tid & 31) == 0) sred[wrp] = s;
    __syncthreads();

    if (wrp == 0) {
        double v = (tid < 16) ? sred[tid] : 0.0;
        #pragma unroll
        for (int off = 8; off > 0; off >>= 1)
            v += __shfl_down_sync(0xffffffffu, v, off);
        if (tid == 0) atomicAdd(&g_loss, v);
    }
}

// ---------------------------------------------------------------------------
__global__ void k_final(float* __restrict__ out_loss, int total_elems)
{
    const float m = (float)(g_loss / (double)total_elems);
    out_loss[0] = __fadd_rn(m, __fmul_rn(0.25f, m));
}

// ---------------------------------------------------------------------------
extern "C" void kernel_launch(void* const* d_in, const int* in_sizes, int n_in,
                              void* d_out, int out_size)
{
    const float* z = (const float*)d_in[0];   // (N, 64) fp32
    const float* w = (const float*)d_in[1];   // (1024, 64) fp32

    const int ND = in_sizes[0];
    const int N  = ND / DIM;                  // 262144

    float* out      = (float*)d_out;
    float* out_zq   = out;                    // N*64 floats
    float* out_loss = out + (size_t)N * DIM;  // 1 float
    float* out_idx  = out_loss + 1;           // N floats

    cudaFuncSetAttribute(k_argmin_mma,
                         cudaFuncAttributeMaxDynamicSharedMemorySize, SMEMSZ);

    k_zero<<<1, 1>>>();
    k_prep_w<<<(KCODE + 255) / 256, 256>>>(w);
    k_prep_z<<<(N * DIM / 4) / 256, 256>>>(z);
    k_argmin_mma<<<N / 256, 256, SMEMSZ>>>(out_idx);
    k_exact<<<256, 256>>>(z, w, out_idx);
    k_gather<<<N / 32, 512>>>(z, w, out_zq);
    k_final<<<1, 1>>>(out_loss, ND);
}